// round 2
// baseline (speedup 1.0000x reference)
#include <cuda_runtime.h>
#include <math.h>

// Causal depthwise conv1d, K=24, T=3000.
// y[b,c,t] = sum_{k=0..23} w[c,k] * x[b,c,t-23+k]
// w[c,k] = beta*exp(log(max(alpha,1e-6))*k)*(1 - u^2/2 + u^4/24), u=theta*k

#define KSZ 24
#define T_LEN 3000
#define SEG 1500          // two segments per row
#define SEG4 (SEG / 4)    // 375 active compute threads
#define NTHREADS 384

__device__ __forceinline__ unsigned long long pk2(float lo, float hi) {
    unsigned long long d;
    asm("mov.b64 %0, {%1, %2};" : "=l"(d) : "f"(lo), "f"(hi));
    return d;
}
__device__ __forceinline__ unsigned long long fma2(unsigned long long a,
                                                   unsigned long long b,
                                                   unsigned long long c) {
    unsigned long long d;
    asm("fma.rn.f32x2 %0, %1, %2, %3;" : "=l"(d) : "l"(a), "l"(b), "l"(c));
    return d;
}
__device__ __forceinline__ float psum(unsigned long long v) {
    float lo, hi;
    asm("mov.b64 {%0, %1}, %2;" : "=f"(lo), "=f"(hi) : "l"(v));
    return lo + hi;
}

__global__ __launch_bounds__(NTHREADS, 2)
void ssm4d_conv_kernel(const float* __restrict__ x,
                       const float* __restrict__ alpha,
                       const float* __restrict__ beta,
                       const float* __restrict__ theta,
                       float* __restrict__ y,
                       int C)
{
    // S[0..23] = halo (zeros for segment 0, previous 24 x values otherwise)
    // S[24+t]  = x[row, tbase + t],  t in [0, SEG)
    __shared__ __align__(16) float S[KSZ + SEG];   // 1524 floats = 6096 B
    __shared__ __align__(16) float sw[KSZ];

    const int c   = blockIdx.x;
    const int b   = blockIdx.y;
    const int s   = blockIdx.z;
    const int tid = threadIdx.x;
    const long rowbase = ((long)b * C + c) * (long)T_LEN;
    const int  tbase   = s * SEG;
    const float* xr = x + rowbase + tbase;

    // halo fill: 24 floats = 6 float4 (STS.128, aligned)
    if (tid < KSZ / 4) {
        float4 h;
        if (s == 0) { h.x = h.y = h.z = h.w = 0.0f; }
        else        { h = reinterpret_cast<const float4*>(xr - KSZ)[tid]; }
        reinterpret_cast<float4*>(S)[tid] = h;
    }
    // data fill: 375 float4 (LDG.128 -> STS.128, both aligned)
    if (tid < SEG4) {
        reinterpret_cast<float4*>(S + KSZ)[tid] =
            reinterpret_cast<const float4*>(xr)[tid];
    }
    // per-channel weights
    if (tid < KSZ) {
        float a  = alpha[c];
        float la = logf(fmaxf(a, 1e-6f));
        float d  = expf(la * (float)tid);
        float u  = theta[c] * (float)tid;
        float u2 = u * u;
        float ph = 1.0f - 0.5f * u2 + (u2 * u2) * (1.0f / 24.0f);
        sw[tid] = beta[c] * d * ph;
    }
    __syncthreads();

    if (tid < SEG4) {
        // weights: 6 broadcast LDS.128, then 12 packed (w2i, w2i+1) pairs
        float wf[KSZ];
#pragma unroll
        for (int j = 0; j < KSZ / 4; j++) {
            float4 wv = reinterpret_cast<const float4*>(sw)[j];
            wf[4 * j + 0] = wv.x; wf[4 * j + 1] = wv.y;
            wf[4 * j + 2] = wv.z; wf[4 * j + 3] = wv.w;
        }
        unsigned long long wp[12];
#pragma unroll
        for (int i = 0; i < 12; i++) wp[i] = pk2(wf[2 * i], wf[2 * i + 1]);

        // window: X[0..27] = S[4*tid .. 4*tid+27], 7 aligned LDS.128
        // (lane stride 16B -> conflict-free). Even pairs land as u64 directly.
        union {
            longlong2 l2[7];
            unsigned long long u[14];
            float f[28];
        } X;
        const longlong2* S2 = reinterpret_cast<const longlong2*>(S + 4 * tid);
#pragma unroll
        for (int j = 0; j < 7; j++) X.l2[j] = S2[j];

        // y_j = sum_{i<12} wp[i] . (X.f[j+1+2i], X.f[j+2+2i])
        //   j=1 -> even pair X.u[i+1];  j=3 -> X.u[i+2]
        //   j=0 -> odd pair O_i = (f[2i+1], f[2i+2]); j=2 -> O_{i+1}
        unsigned long long a0 = 0ull, a1 = 0ull, a2 = 0ull, a3 = 0ull;
#pragma unroll
        for (int i = 0; i <= 12; i++) {
            unsigned long long O = pk2(X.f[2 * i + 1], X.f[2 * i + 2]);
            if (i < 12) {
                a0 = fma2(wp[i], O,          a0);
                a1 = fma2(wp[i], X.u[i + 1], a1);
                a3 = fma2(wp[i], X.u[i + 2], a3);
            }
            if (i >= 1) {
                a2 = fma2(wp[i - 1], O, a2);
            }
        }

        float4 o;
        o.x = psum(a0); o.y = psum(a1); o.z = psum(a2); o.w = psum(a3);
        reinterpret_cast<float4*>(y + rowbase + tbase)[tid] = o;
    }
}

extern "C" void kernel_launch(void* const* d_in, const int* in_sizes, int n_in,
                              void* d_out, int out_size)
{
    const float* x     = (const float*)d_in[0];
    const float* alpha = (const float*)d_in[1];
    const float* beta  = (const float*)d_in[2];
    const float* theta = (const float*)d_in[3];
    float* y = (float*)d_out;

    const int C = in_sizes[1];                 // 1024
    const int B = in_sizes[0] / (C * T_LEN);   // 16

    dim3 grid(C, B, T_LEN / SEG);
    ssm4d_conv_kernel<<<grid, NTHREADS>>>(x, alpha, beta, theta, y, C);
}

// round 4
// speedup vs baseline: 1.9217x; 1.9217x over previous
#include <cuda_runtime.h>
#include <math.h>

// Causal depthwise conv1d, K=24, T=3000.
// y[b,c,t] = sum_{k=0..23} w[c,k] * x[b,c,t-23+k]
// w[c,k] = beta*exp(log(max(alpha,1e-6))*k)*(1 - u^2/2 + u^4/24), u=theta*k

#define KSZ 24
#define T_LEN 3000
#define R_OUT 12
#define NACT (T_LEN / R_OUT)   // 250 active compute threads
#define NTHREADS 256
#define NVEC (T_LEN / 4)       // 750 float4 per row

__global__ __launch_bounds__(NTHREADS)
void ssm4d_conv_kernel(const float* __restrict__ x,
                       const float* __restrict__ alpha,
                       const float* __restrict__ beta,
                       const float* __restrict__ theta,
                       float* __restrict__ y,
                       int C)
{
    // S[0..23]  = zeros (24-wide pad keeps all STS.128 aligned)
    // S[24 + t] = x[row, t]
    // Identity: y[t] = sum_k w[k] * S[t + 1 + k]   (pad is 24, kernel span 23)
    __shared__ __align__(16) float S[KSZ + T_LEN];   // 3024 floats = 12096 B
    __shared__ __align__(16) float sw[KSZ];

    const int c   = blockIdx.x;
    const int b   = blockIdx.y;
    const int tid = threadIdx.x;
    const long rowbase = ((long)b * C + c) * (long)T_LEN;

    // ---- fill: aligned LDG.128 -> STS.128 ----
    const float4* xv = reinterpret_cast<const float4*>(x + rowbase);
    float4*       Sd = reinterpret_cast<float4*>(S + KSZ);
#pragma unroll
    for (int i = tid; i < NVEC; i += NTHREADS) Sd[i] = xv[i];
    if (tid < KSZ / 4)
        reinterpret_cast<float4*>(S)[tid] = make_float4(0.f, 0.f, 0.f, 0.f);

    // ---- per-channel weights ----
    if (tid < KSZ) {
        float a  = alpha[c];
        float la = logf(fmaxf(a, 1e-6f));
        float d  = expf(la * (float)tid);
        float u  = theta[c] * (float)tid;
        float u2 = u * u;
        float ph = 1.0f - 0.5f * u2 + (u2 * u2) * (1.0f / 24.0f);
        sw[tid] = beta[c] * d * ph;
    }
    __syncthreads();

    if (tid < NACT) {
        // weights: 6 broadcast LDS.128 (conflict-free broadcast)
        float w[KSZ];
#pragma unroll
        for (int j = 0; j < KSZ / 4; j++) {
            float4 wv = reinterpret_cast<const float4*>(sw)[j];
            w[4 * j + 0] = wv.x; w[4 * j + 1] = wv.y;
            w[4 * j + 2] = wv.z; w[4 * j + 3] = wv.w;
        }

        // window: X[0..35] = S[12*tid .. 12*tid+35]
        // 9 LDS.128, lane stride 48B -> all 32 banks hit exactly once per
        // 8-lane phase: conflict-free.
        float X[R_OUT + KSZ];   // 36
        const float4* S4 = reinterpret_cast<const float4*>(&S[R_OUT * tid]);
#pragma unroll
        for (int j = 0; j < 9; j++) {
            float4 v = S4[j];
            X[4 * j + 0] = v.x; X[4 * j + 1] = v.y;
            X[4 * j + 2] = v.z; X[4 * j + 3] = v.w;
        }

        // y[12*tid + j] = sum_k w[k] * X[j + 1 + k]   (max index 35)
        float acc[R_OUT];
#pragma unroll
        for (int j = 0; j < R_OUT; j++) acc[j] = 0.0f;
#pragma unroll
        for (int k = 0; k < KSZ; k++) {
            float wk = w[k];
#pragma unroll
            for (int j = 0; j < R_OUT; j++)
                acc[j] = fmaf(wk, X[j + 1 + k], acc[j]);
        }

        // store 12 outputs: 3 aligned STG.128
        float4* yo = reinterpret_cast<float4*>(y + rowbase + R_OUT * tid);
#pragma unroll
        for (int j = 0; j < 3; j++) {
            float4 o;
            o.x = acc[4 * j + 0]; o.y = acc[4 * j + 1];
            o.z = acc[4 * j + 2]; o.w = acc[4 * j + 3];
            yo[j] = o;
        }
    }
}

extern "C" void kernel_launch(void* const* d_in, const int* in_sizes, int n_in,
                              void* d_out, int out_size)
{
    const float* x     = (const float*)d_in[0];
    const float* alpha = (const float*)d_in[1];
    const float* beta  = (const float*)d_in[2];
    const float* theta = (const float*)d_in[3];
    float* y = (float*)d_out;

    const int C = in_sizes[1];                 // 1024
    const int B = in_sizes[0] / (C * T_LEN);   // 16

    dim3 grid(C, B);
    ssm4d_conv_kernel<<<grid, NTHREADS>>>(x, alpha, beta, theta, y, C);
}